// round 13
// baseline (speedup 1.0000x reference)
#include <cuda_runtime.h>
#include <cuda_bf16.h>
#include <math.h>
#include <stdint.h>

// ---------------- problem constants ----------------
#define BSZ 2
#define TSZ 1024
#define CSZ 768
#define LSZ 12
#define HSZ 12
#define HDSZ 64
#define VSZ 50257
#define BT (BSZ*TSZ)

// ---------------- device scratch (no allocation allowed) ----------------
__device__ float g_x  [BT*CSZ];      // residual stream
__device__ float g_h  [BT*CSZ];      // layernorm output
__device__ float g_qkv[BT*3*CSZ];    // qkv projection
__device__ float g_ao [BT*CSZ];      // attention output (pre-proj)
__device__ float g_hid[BT*4*CSZ];    // MLP hidden

// ---------------- reductions ----------------
__device__ __forceinline__ float warpReduceSum(float v){
    #pragma unroll
    for (int o = 16; o > 0; o >>= 1) v += __shfl_xor_sync(0xffffffffu, v, o);
    return v;
}
__device__ __forceinline__ float warpReduceMax(float v){
    #pragma unroll
    for (int o = 16; o > 0; o >>= 1) v = fmaxf(v, __shfl_xor_sync(0xffffffffu, v, o));
    return v;
}
__device__ __forceinline__ float blockReduceSum(float v, float* sh){
    int lane = threadIdx.x & 31, w = threadIdx.x >> 5;
    v = warpReduceSum(v);
    __syncthreads();
    if (lane == 0) sh[w] = v;
    __syncthreads();
    int nw = blockDim.x >> 5;
    float r = (threadIdx.x < nw) ? sh[threadIdx.x] : 0.0f;
    if (w == 0){ r = warpReduceSum(r); if (lane == 0) sh[0] = r; }
    __syncthreads();
    return sh[0];
}
__device__ __forceinline__ float blockReduceMax(float v, float* sh){
    int lane = threadIdx.x & 31, w = threadIdx.x >> 5;
    v = warpReduceMax(v);
    __syncthreads();
    if (lane == 0) sh[w] = v;
    __syncthreads();
    int nw = blockDim.x >> 5;
    float r = (threadIdx.x < nw) ? sh[threadIdx.x] : -1e30f;
    if (w == 0){ r = warpReduceMax(r); if (lane == 0) sh[0] = r; }
    __syncthreads();
    return sh[0];
}

// ---------------- embedding ----------------
__global__ void embed_kernel(const int* __restrict__ idx,
                             const float* __restrict__ wte,
                             const float* __restrict__ wpe,
                             float* __restrict__ x){
    int i = blockIdx.x * blockDim.x + threadIdx.x;
    if (i >= BT*CSZ) return;
    int c  = i % CSZ;
    int bt = i / CSZ;
    int t  = bt % TSZ;
    x[i] = wte[(size_t)idx[bt]*CSZ + c] + wpe[(size_t)t*CSZ + c];
}

// ---------------- layernorm ----------------
__global__ void __launch_bounds__(256) ln_kernel(const float* __restrict__ x,
                                                 const float* __restrict__ g,
                                                 const float* __restrict__ b,
                                                 float* __restrict__ out){
    __shared__ float sh[32];
    int row = blockIdx.x, tid = threadIdx.x;
    const float* xr = x + (size_t)row*CSZ;
    float v0 = xr[tid], v1 = xr[tid+256], v2 = xr[tid+512];
    float mean = blockReduceSum(v0+v1+v2, sh) * (1.0f/CSZ);
    float d0 = v0-mean, d1 = v1-mean, d2 = v2-mean;
    float var = blockReduceSum(d0*d0 + d1*d1 + d2*d2, sh) * (1.0f/CSZ);
    float rs = rsqrtf(var + 1e-5f);
    float* orow = out + (size_t)row*CSZ;
    orow[tid    ] = d0*rs*g[tid    ] + b[tid    ];
    orow[tid+256] = d1*rs*g[tid+256] + b[tid+256];
    orow[tid+512] = d2*rs*g[tid+512] + b[tid+512];
}

// =====================================================================
// bf16 split-precision tensor-core GEMM (hiA*hiB + hiA*loB + loA*hiB)
// Term-major MMA issue: any accumulator reuse is >=16 MMAs apart, so
// tensor-result latency is covered by independent work.
// C[M,N] = A[M,K] @ B (+bias +res, optional exact GELU)
// TRANSB=0: B is [K,N] row-major (N multiple of 128).
// TRANSB=1: B is [N,K] row-major (logits head; N guarded).
// M multiple of 128, K multiple of 32.
// =====================================================================
#define BM 128
#define BN 128
#define BK 32
#define APAD 8
#define BPAD 8

__device__ __forceinline__ void ldsm4(uint32_t* r, const __nv_bfloat16* p){
    uint32_t addr = (uint32_t)__cvta_generic_to_shared(p);
    asm volatile("ldmatrix.sync.aligned.m8n8.x4.shared.b16 {%0,%1,%2,%3}, [%4];"
        : "=r"(r[0]), "=r"(r[1]), "=r"(r[2]), "=r"(r[3]) : "r"(addr));
}
__device__ __forceinline__ void ldsm4t(uint32_t* r, const __nv_bfloat16* p){
    uint32_t addr = (uint32_t)__cvta_generic_to_shared(p);
    asm volatile("ldmatrix.sync.aligned.m8n8.x4.trans.shared.b16 {%0,%1,%2,%3}, [%4];"
        : "=r"(r[0]), "=r"(r[1]), "=r"(r[2]), "=r"(r[3]) : "r"(addr));
}
// NOTE: non-volatile — pure register op, lets ptxas schedule/pipeline MMAs.
__device__ __forceinline__ void mma_bf16(float* c, const uint32_t* a, const uint32_t* b){
    asm("mma.sync.aligned.m16n8k16.row.col.f32.bf16.bf16.f32 "
        "{%0,%1,%2,%3}, {%4,%5,%6,%7}, {%8,%9}, {%0,%1,%2,%3};\n"
        : "+f"(c[0]), "+f"(c[1]), "+f"(c[2]), "+f"(c[3])
        : "r"(a[0]), "r"(a[1]), "r"(a[2]), "r"(a[3]), "r"(b[0]), "r"(b[1]));
}

// convert 8 floats (two float4) to hi/lo bf16 planes, 16B store each
__device__ __forceinline__ void cvt_store8(__nv_bfloat16* hip, __nv_bfloat16* lop,
                                           float4 v0, float4 v1){
    float f[8] = {v0.x, v0.y, v0.z, v0.w, v1.x, v1.y, v1.z, v1.w};
    uint32_t h[4], l[4];
    #pragma unroll
    for (int i = 0; i < 4; i++){
        float a = f[2*i], b = f[2*i+1];
        __nv_bfloat162 hb = __floats2bfloat162_rn(a, b);
        float2 hf = __bfloat1622float2(hb);
        __nv_bfloat162 lb = __floats2bfloat162_rn(a - hf.x, b - hf.y);
        h[i] = *(uint32_t*)&hb;
        l[i] = *(uint32_t*)&lb;
    }
    *(uint4*)hip = make_uint4(h[0], h[1], h[2], h[3]);
    *(uint4*)lop = make_uint4(l[0], l[1], l[2], l[3]);
}

template<int TRANSB>
__global__ void __launch_bounds__(256) gemm_kernel(
    const float* __restrict__ A, const float* __restrict__ B,
    const float* __restrict__ bias, const float* __restrict__ res,
    float* __restrict__ Cmat, int M, int N, int K, int doGelu)
{
    constexpr int ALD = BK + APAD;                    // 40 halves
    constexpr int BROWS = TRANSB ? BN : BK;
    constexpr int BLD   = TRANSB ? (BK + APAD) : (BN + BPAD);   // 40 or 136

    __shared__ __align__(16) __nv_bfloat16 As_hi[BM*ALD];
    __shared__ __align__(16) __nv_bfloat16 As_lo[BM*ALD];
    __shared__ __align__(16) __nv_bfloat16 Bs_hi[BROWS*BLD];
    __shared__ __align__(16) __nv_bfloat16 Bs_lo[BROWS*BLD];

    int tid = threadIdx.x;
    int lane = tid & 31, warp = tid >> 5;
    int bm = blockIdx.y * BM, bn = blockIdx.x * BN;
    int wm = (warp >> 2) * 64;      // warp grid: 2 (m) x 4 (n), warp tile 64x32
    int wn = (warp & 3) * 32;

    float acc[4][4][4];             // [mtile16][ntile8][frag]
    #pragma unroll
    for (int i = 0; i < 4; i++)
        #pragma unroll
        for (int j = 0; j < 4; j++)
            #pragma unroll
            for (int f = 0; f < 4; f++) acc[i][j][f] = 0.0f;

    // global-load assignments
    int arow = tid >> 1, akc = (tid & 1) * 16;        // A: 128 rows x 32 k
    const float* aptr = A + (size_t)(bm + arow)*K + akc;
    int bro, bco; const float* bptr; bool bvalid = true;
    if (!TRANSB){
        bro = tid >> 3; bco = (tid & 7) * 16;          // B: 32 k-rows x 128 n
        bptr = B + (size_t)bro*N + bn + bco;
    } else {
        bro = tid >> 1; bco = (tid & 1) * 16;          // B: 128 n-rows x 32 k
        int gn = bn + bro;
        bvalid = (gn < N);
        bptr = B + (size_t)gn*K + bco;
    }

    float4 pa[4], pb[4];
    // prologue: prefetch tile 0
    #pragma unroll
    for (int v = 0; v < 4; v++) pa[v] = *(const float4*)(aptr + v*4);
    #pragma unroll
    for (int v = 0; v < 4; v++)
        pb[v] = bvalid ? *(const float4*)(bptr + v*4) : make_float4(0,0,0,0);

    for (int k0 = 0; k0 < K; k0 += BK){
        // ---- convert + store current tile ----
        cvt_store8(&As_hi[arow*ALD + akc],     &As_lo[arow*ALD + akc],     pa[0], pa[1]);
        cvt_store8(&As_hi[arow*ALD + akc + 8], &As_lo[arow*ALD + akc + 8], pa[2], pa[3]);
        cvt_store8(&Bs_hi[bro*BLD + bco],      &Bs_lo[bro*BLD + bco],      pb[0], pb[1]);
        cvt_store8(&Bs_hi[bro*BLD + bco + 8],  &Bs_lo[bro*BLD + bco + 8],  pb[2], pb[3]);
        __syncthreads();

        // ---- prefetch next tile (LDGs overlap the MMA section) ----
        if (k0 + BK < K){
            const float* an = aptr + k0 + BK;
            #pragma unroll
            for (int v = 0; v < 4; v++) pa[v] = *(const float4*)(an + v*4);
            const float* bnp = bptr + (TRANSB ? (k0 + BK)
                                              : (size_t)(k0 + BK)*N);
            #pragma unroll
            for (int v = 0; v < 4; v++)
                pb[v] = bvalid ? *(const float4*)(bnp + v*4) : make_float4(0,0,0,0);
        }

        // ---- compute: 2 k-steps of 16, term-major MMA issue ----
        #pragma unroll
        for (int ks = 0; ks < 2; ks++){
            uint32_t ah[4][4], al[4][4], bh[4][2], bl[4][2];
            // B fragments
            #pragma unroll
            for (int j = 0; j < 2; j++){
                uint32_t r[4];
                if (!TRANSB){
                    int row = ks*16 + (lane & 15);
                    int col = wn + j*16 + (lane >> 4)*8;
                    ldsm4t(r, &Bs_hi[row*BLD + col]);
                    bh[2*j][0]=r[0]; bh[2*j][1]=r[1]; bh[2*j+1][0]=r[2]; bh[2*j+1][1]=r[3];
                    ldsm4t(r, &Bs_lo[row*BLD + col]);
                    bl[2*j][0]=r[0]; bl[2*j][1]=r[1]; bl[2*j+1][0]=r[2]; bl[2*j+1][1]=r[3];
                } else {
                    int row = wn + j*16 + (lane & 15);
                    int col = ks*16 + (lane >> 4)*8;
                    ldsm4(r, &Bs_hi[row*BLD + col]);
                    bh[2*j][0]=r[0]; bh[2*j][1]=r[2]; bh[2*j+1][0]=r[1]; bh[2*j+1][1]=r[3];
                    ldsm4(r, &Bs_lo[row*BLD + col]);
                    bl[2*j][0]=r[0]; bl[2*j][1]=r[2]; bl[2*j+1][0]=r[1]; bl[2*j+1][1]=r[3];
                }
            }
            // A fragments
            #pragma unroll
            for (int mt = 0; mt < 4; mt++){
                int row = wm + mt*16 + (lane & 15);
                int col = ks*16 + (lane >> 4)*8;
                ldsm4(ah[mt], &As_hi[row*ALD + col]);
                ldsm4(al[mt], &As_lo[row*ALD + col]);
            }
            // term 1: hi*hi — 16 independent accumulators
            #pragma unroll
            for (int mt = 0; mt < 4; mt++)
                #pragma unroll
                for (int nt = 0; nt < 4; nt++)
                    mma_bf16(acc[mt][nt], ah[mt], bh[nt]);
            // term 2: hi*lo
            #pragma unroll
            for (int mt = 0; mt < 4; mt++)
                #pragma unroll
                for (int nt = 0; nt < 4; nt++)
                    mma_bf16(acc[mt][nt], ah[mt], bl[nt]);
            // term 3: lo*hi
            #pragma unroll
            for (int mt = 0; mt < 4; mt++)
                #pragma unroll
                for (int nt = 0; nt < 4; nt++)
                    mma_bf16(acc[mt][nt], al[mt], bh[nt]);
        }
        __syncthreads();
    }

    // ---- epilogue ----
    #pragma unroll
    for (int mt = 0; mt < 4; mt++){
        #pragma unroll
        for (int nt = 0; nt < 4; nt++){
            int row0 = bm + wm + mt*16 + (lane >> 2);
            int col0 = bn + wn + nt*8 + 2*(lane & 3);
            #pragma unroll
            for (int f = 0; f < 4; f++){
                int gm = row0 + ((f >= 2) ? 8 : 0);
                int gn = col0 + (f & 1);
                if (gn < N){
                    float v = acc[mt][nt][f];
                    if (bias) v += bias[gn];
                    if (res)  v += res[(size_t)gm*N + gn];
                    if (doGelu) v = 0.5f*v*(1.0f + erff(v*0.70710678118654752f));
                    Cmat[(size_t)gm*N + gn] = v;
                }
            }
        }
    }
}

// ---------------- fused causal attention: one block per (b,h,t) ----------------
__global__ void __launch_bounds__(128) attn_kernel(const float* __restrict__ qkv,
                                                   float* __restrict__ out){
    int t = blockIdx.x, h = blockIdx.y, b = blockIdx.z;
    __shared__ float q[HDSZ];
    __shared__ float p[TSZ];
    __shared__ float sh[32];
    int tid = threadIdx.x;

    const float* base = qkv + (size_t)b*TSZ*3*CSZ;
    const float* qr = base + (size_t)t*3*CSZ + h*3*HDSZ;
    if (tid < HDSZ) q[tid] = qr[tid] * 0.125f;   // 1/sqrt(64) folded into q
    __syncthreads();

    float mymax = -1e30f;
    for (int s = tid; s <= t; s += 128){
        const float* kr = base + (size_t)s*3*CSZ + h*3*HDSZ + HDSZ;
        float d = 0.0f;
        #pragma unroll
        for (int i = 0; i < HDSZ; i++) d = fmaf(q[i], kr[i], d);
        p[s] = d;
        mymax = fmaxf(mymax, d);
    }
    float mx = blockReduceMax(mymax, sh);

    float mysum = 0.0f;
    for (int s = tid; s <= t; s += 128){
        float e = __expf(p[s] - mx);
        p[s] = e;
        mysum += e;
    }
    float inv = 1.0f / blockReduceSum(mysum, sh);

    if (tid < HDSZ){
        float acc = 0.0f;
        const float* vr = base + h*3*HDSZ + 2*HDSZ + tid;
        for (int s = 0; s <= t; s++)
            acc = fmaf(p[s], vr[(size_t)s*3*CSZ], acc);
        out[((size_t)(b*TSZ + t))*CSZ + h*HDSZ + tid] = acc * inv;
    }
}

// ---------------- launch ----------------
extern "C" void kernel_launch(void* const* d_in, const int* in_sizes, int n_in,
                              void* d_out, int out_size)
{
    const int*   idx    = (const int*)  d_in[0];
    const float* wte    = (const float*)d_in[1];
    const float* wpe    = (const float*)d_in[2];
    const float* ln1_g  = (const float*)d_in[3];
    const float* ln1_b  = (const float*)d_in[4];
    const float* attn_w = (const float*)d_in[5];
    const float* attn_b = (const float*)d_in[6];
    const float* proj_w = (const float*)d_in[7];
    const float* proj_b = (const float*)d_in[8];
    const float* ln2_g  = (const float*)d_in[9];
    const float* ln2_b  = (const float*)d_in[10];
    const float* fc_w   = (const float*)d_in[11];
    const float* fc_b   = (const float*)d_in[12];
    const float* fp_w   = (const float*)d_in[13];
    const float* fp_b   = (const float*)d_in[14];
    const float* lnf_g  = (const float*)d_in[15];
    const float* lnf_b  = (const float*)d_in[16];
    float* out = (float*)d_out;

    float *x, *h, *qkv, *ao, *hid;
    cudaGetSymbolAddress((void**)&x,   g_x);
    cudaGetSymbolAddress((void**)&h,   g_h);
    cudaGetSymbolAddress((void**)&qkv, g_qkv);
    cudaGetSymbolAddress((void**)&ao,  g_ao);
    cudaGetSymbolAddress((void**)&hid, g_hid);

    embed_kernel<<<(BT*CSZ + 255)/256, 256>>>(idx, wte, wpe, x);

    for (int l = 0; l < LSZ; l++){
        // attention
        ln_kernel<<<BT, 256>>>(x, ln1_g + (size_t)l*CSZ, ln1_b + (size_t)l*CSZ, h);
        gemm_kernel<0><<<dim3(3*CSZ/BN, BT/BM), 256>>>(
            h, attn_w + (size_t)l*CSZ*3*CSZ, attn_b + (size_t)l*3*CSZ,
            nullptr, qkv, BT, 3*CSZ, CSZ, 0);
        attn_kernel<<<dim3(TSZ, HSZ, BSZ), 128>>>(qkv, ao);
        gemm_kernel<0><<<dim3(CSZ/BN, BT/BM), 256>>>(
            ao, proj_w + (size_t)l*CSZ*CSZ, proj_b + (size_t)l*CSZ,
            x, x, BT, CSZ, CSZ, 0);
        // MLP
        ln_kernel<<<BT, 256>>>(x, ln2_g + (size_t)l*CSZ, ln2_b + (size_t)l*CSZ, h);
        gemm_kernel<0><<<dim3(4*CSZ/BN, BT/BM), 256>>>(
            h, fc_w + (size_t)l*CSZ*4*CSZ, fc_b + (size_t)l*4*CSZ,
            nullptr, hid, BT, 4*CSZ, CSZ, 1);
        gemm_kernel<0><<<dim3(CSZ/BN, BT/BM), 256>>>(
            hid, fp_w + (size_t)l*4*CSZ*CSZ, fp_b + (size_t)l*CSZ,
            x, x, BT, CSZ, 4*CSZ, 0);
    }

    // final LN + tied-embedding logits head (wte is [V, C] = [N, K])
    ln_kernel<<<BT, 256>>>(x, lnf_g, lnf_b, h);
    gemm_kernel<1><<<dim3((VSZ + BN - 1)/BN, BT/BM), 256>>>(
        h, wte, nullptr, nullptr, out, BT, VSZ, CSZ, 0);
}

// round 15
// speedup vs baseline: 3.4149x; 3.4149x over previous
#include <cuda_runtime.h>
#include <cuda_bf16.h>
#include <math.h>
#include <stdint.h>

// ---------------- problem constants ----------------
#define BSZ 2
#define TSZ 1024
#define CSZ 768
#define LSZ 12
#define HSZ 12
#define HDSZ 64
#define VSZ 50257
#define BT (BSZ*TSZ)

// ---------------- device scratch (no allocation allowed) ----------------
__device__ float g_x  [BT*CSZ];        // residual stream (fp32)
__device__ float g_qkv[BT*3*CSZ];      // qkv projection (fp32)
__device__ __nv_bfloat16 g_h_hi [BT*CSZ],   g_h_lo [BT*CSZ];    // ln out planes
__device__ __nv_bfloat16 g_ao_hi[BT*CSZ],   g_ao_lo[BT*CSZ];    // attn out planes
__device__ __nv_bfloat16 g_hid_hi[BT*4*CSZ], g_hid_lo[BT*4*CSZ];// MLP hidden planes

// pre-transposed/converted weights: [N][K] K-major bf16, hi & lo planes
__device__ __nv_bfloat16 g_attnT_hi[LSZ*3*CSZ*CSZ];
__device__ __nv_bfloat16 g_attnT_lo[LSZ*3*CSZ*CSZ];
__device__ __nv_bfloat16 g_projT_hi[LSZ*CSZ*CSZ];
__device__ __nv_bfloat16 g_projT_lo[LSZ*CSZ*CSZ];
__device__ __nv_bfloat16 g_fcT_hi  [LSZ*4*CSZ*CSZ];
__device__ __nv_bfloat16 g_fcT_lo  [LSZ*4*CSZ*CSZ];
__device__ __nv_bfloat16 g_fpT_hi  [LSZ*CSZ*4*CSZ];
__device__ __nv_bfloat16 g_fpT_lo  [LSZ*CSZ*4*CSZ];
__device__ __nv_bfloat16 g_wte_hi  [VSZ*CSZ];
__device__ __nv_bfloat16 g_wte_lo  [VSZ*CSZ];

// ---------------- small helpers ----------------
__device__ __forceinline__ float warpReduceSum(float v){
    #pragma unroll
    for (int o = 16; o > 0; o >>= 1) v += __shfl_xor_sync(0xffffffffu, v, o);
    return v;
}
__device__ __forceinline__ float blockReduceSum(float v, float* sh){
    int lane = threadIdx.x & 31, w = threadIdx.x >> 5;
    v = warpReduceSum(v);
    __syncthreads();
    if (lane == 0) sh[w] = v;
    __syncthreads();
    int nw = blockDim.x >> 5;
    float r = (threadIdx.x < nw) ? sh[threadIdx.x] : 0.0f;
    if (w == 0){ r = warpReduceSum(r); if (lane == 0) sh[0] = r; }
    __syncthreads();
    return sh[0];
}
__device__ __forceinline__ void split_bf16(float v, __nv_bfloat16& h, __nv_bfloat16& l){
    h = __float2bfloat16(v);
    l = __float2bfloat16(v - __bfloat162float(h));
}

// ---------------- embedding ----------------
__global__ void embed_kernel(const int* __restrict__ idx,
                             const float* __restrict__ wte,
                             const float* __restrict__ wpe,
                             float* __restrict__ x){
    int i = blockIdx.x * blockDim.x + threadIdx.x;
    if (i >= BT*CSZ) return;
    int c  = i % CSZ;
    int bt = i / CSZ;
    int t  = bt % TSZ;
    x[i] = wte[(size_t)idx[bt]*CSZ + c] + wpe[(size_t)t*CSZ + c];
}

// ---------------- layernorm -> bf16 hi/lo planes ----------------
__global__ void __launch_bounds__(256) ln_kernel(const float* __restrict__ x,
                                                 const float* __restrict__ g,
                                                 const float* __restrict__ b,
                                                 __nv_bfloat16* __restrict__ oh,
                                                 __nv_bfloat16* __restrict__ ol){
    __shared__ float sh[32];
    int row = blockIdx.x, tid = threadIdx.x;
    const float* xr = x + (size_t)row*CSZ;
    float v0 = xr[tid], v1 = xr[tid+256], v2 = xr[tid+512];
    float mean = blockReduceSum(v0+v1+v2, sh) * (1.0f/CSZ);
    float d0 = v0-mean, d1 = v1-mean, d2 = v2-mean;
    float var = blockReduceSum(d0*d0 + d1*d1 + d2*d2, sh) * (1.0f/CSZ);
    float rs = rsqrtf(var + 1e-5f);
    size_t base = (size_t)row*CSZ;
    #pragma unroll
    for (int j = 0; j < 3; j++){
        int c = tid + j*256;
        float d = (j==0)?d0:((j==1)?d1:d2);
        float val = d*rs*g[c] + b[c];
        __nv_bfloat16 h, l;
        split_bf16(val, h, l);
        oh[base + c] = h;
        ol[base + c] = l;
    }
}

// ---------------- weight transpose + hi/lo bf16 convert ----------------
__global__ void transcvt_kernel(const float* __restrict__ W,
                                __nv_bfloat16* __restrict__ Ohi,
                                __nv_bfloat16* __restrict__ Olo, int K, int N){
    __shared__ float t[32][33];
    int l = blockIdx.z;
    const float* Wl = W + (size_t)l*K*N;
    __nv_bfloat16* Hl = Ohi + (size_t)l*K*N;
    __nv_bfloat16* Ll = Olo + (size_t)l*K*N;
    int n0 = blockIdx.x*32, k0 = blockIdx.y*32;
    int tx = threadIdx.x, ty = threadIdx.y;
    #pragma unroll
    for (int i = ty; i < 32; i += 8)
        t[i][tx] = Wl[(size_t)(k0+i)*N + n0 + tx];
    __syncthreads();
    #pragma unroll
    for (int i = ty; i < 32; i += 8){
        float v = t[tx][i];
        __nv_bfloat16 h, lo;
        split_bf16(v, h, lo);
        Hl[(size_t)(n0+i)*K + k0 + tx] = h;
        Ll[(size_t)(n0+i)*K + k0 + tx] = lo;
    }
}

__global__ void cvt_kernel(const float* __restrict__ src,
                           __nv_bfloat16* __restrict__ hi,
                           __nv_bfloat16* __restrict__ lo, int n){
    int i = blockIdx.x * blockDim.x + threadIdx.x;
    if (i >= n) return;
    __nv_bfloat16 h, l;
    split_bf16(src[i], h, l);
    hi[i] = h; lo[i] = l;
}

// =====================================================================
// bf16 split GEMM, cp.async double-buffered.
// C[M,N] = A[M,K] @ B^T ; A planes [M][K], B planes [N][K], all K-major bf16.
// 3 terms: hiA*hiB + hiA*loB + loA*hiB, fp32 accumulate.
// M%128==0, K%32==0, N guarded.
// =====================================================================
#define LDSH 40                       // halves per smem row (80 bytes)
#define PLANE_BYTES (128*80)          // 10240
#define STAGE_BYTES (4*PLANE_BYTES)   // 40960
#define GSMEM (2*STAGE_BYTES)         // 81920

__device__ __forceinline__ void ldsm4(uint32_t* r, const __nv_bfloat16* p){
    uint32_t addr = (uint32_t)__cvta_generic_to_shared(p);
    asm volatile("ldmatrix.sync.aligned.m8n8.x4.shared.b16 {%0,%1,%2,%3}, [%4];"
        : "=r"(r[0]), "=r"(r[1]), "=r"(r[2]), "=r"(r[3]) : "r"(addr));
}
__device__ __forceinline__ void mma_bf16(float* c, const uint32_t* a, const uint32_t* b){
    asm("mma.sync.aligned.m16n8k16.row.col.f32.bf16.bf16.f32 "
        "{%0,%1,%2,%3}, {%4,%5,%6,%7}, {%8,%9}, {%0,%1,%2,%3};\n"
        : "+f"(c[0]), "+f"(c[1]), "+f"(c[2]), "+f"(c[3])
        : "r"(a[0]), "r"(a[1]), "r"(a[2]), "r"(a[3]), "r"(b[0]), "r"(b[1]));
}
__device__ __forceinline__ void cp16(uint32_t dst, const void* src, bool pred){
    int sz = pred ? 16 : 0;
    asm volatile("cp.async.cg.shared.global [%0], [%1], 16, %2;\n"
        :: "r"(dst), "l"(src), "r"(sz));
}
__device__ __forceinline__ void cp_commit(){
    asm volatile("cp.async.commit_group;\n" ::: "memory");
}
template<int NW> __device__ __forceinline__ void cp_wait(){
    asm volatile("cp.async.wait_group %0;\n" :: "n"(NW) : "memory");
}

__device__ __forceinline__ void fill_stage(uint32_t s0,
    const __nv_bfloat16* Ahi, const __nv_bfloat16* Alo,
    const __nv_bfloat16* Bhi, const __nv_bfloat16* Blo,
    int bm, int bn, int k0, int K, int N, int tid)
{
    #pragma unroll
    for (int i = 0; i < 8; i++){
        int idx = tid + i*256;              // 0..2047
        int sel = idx >> 9;                 // 0:Ahi 1:Alo 2:Bhi 3:Blo
        int r   = (idx >> 2) & 127;
        int ch  = idx & 3;
        uint32_t dst = s0 + sel*PLANE_BYTES + r*80 + ch*16;
        const __nv_bfloat16* base;
        int grow; bool ok = true;
        if (sel < 2){ base = sel ? Alo : Ahi; grow = bm + r; }
        else        { base = (sel & 1) ? Blo : Bhi; grow = bn + r; ok = grow < N; }
        cp16(dst, base + (size_t)grow*K + k0 + ch*8, ok);
    }
}

__global__ void __launch_bounds__(256) gemm2(
    const __nv_bfloat16* __restrict__ Ahi, const __nv_bfloat16* __restrict__ Alo,
    const __nv_bfloat16* __restrict__ Bhi, const __nv_bfloat16* __restrict__ Blo,
    const float* __restrict__ bias, const float* __restrict__ res,
    float* __restrict__ Cf, __nv_bfloat16* __restrict__ Chi, __nv_bfloat16* __restrict__ Clo,
    int M, int N, int K, int doGelu)
{
    extern __shared__ char smem[];
    uint32_t sb = (uint32_t)__cvta_generic_to_shared(smem);
    int tid = threadIdx.x, lane = tid & 31, warp = tid >> 5;
    int bm = blockIdx.y * 128, bn = blockIdx.x * 128;
    int wm = (warp >> 2) * 64;     // warp grid 2(m) x 4(n), warp tile 64x32
    int wn = (warp & 3) * 32;

    float acc[4][4][4];
    #pragma unroll
    for (int i = 0; i < 4; i++)
        #pragma unroll
        for (int j = 0; j < 4; j++)
            #pragma unroll
            for (int f = 0; f < 4; f++) acc[i][j][f] = 0.0f;

    int niter = K / 32;
    fill_stage(sb, Ahi, Alo, Bhi, Blo, bm, bn, 0, K, N, tid);
    cp_commit();

    for (int it = 0; it < niter; it++){
        if (it + 1 < niter){
            fill_stage(sb + ((it+1)&1)*STAGE_BYTES, Ahi, Alo, Bhi, Blo,
                       bm, bn, (it+1)*32, K, N, tid);
            cp_commit();
            cp_wait<1>();
        } else {
            cp_wait<0>();
        }
        __syncthreads();

        const char* st = smem + (it & 1)*STAGE_BYTES;
        const __nv_bfloat16* As_hi = (const __nv_bfloat16*)(st);
        const __nv_bfloat16* As_lo = (const __nv_bfloat16*)(st + PLANE_BYTES);
        const __nv_bfloat16* Bs_hi = (const __nv_bfloat16*)(st + 2*PLANE_BYTES);
        const __nv_bfloat16* Bs_lo = (const __nv_bfloat16*)(st + 3*PLANE_BYTES);

        #pragma unroll
        for (int ks = 0; ks < 2; ks++){
            uint32_t ah[4][4], al[4][4], bh[4][2], bl[4][2];
            #pragma unroll
            for (int j = 0; j < 2; j++){
                uint32_t r[4];
                int row = wn + j*16 + (lane & 15);
                int col = ks*16 + (lane >> 4)*8;
                ldsm4(r, Bs_hi + row*LDSH + col);
                bh[2*j][0]=r[0]; bh[2*j][1]=r[2]; bh[2*j+1][0]=r[1]; bh[2*j+1][1]=r[3];
                ldsm4(r, Bs_lo + row*LDSH + col);
                bl[2*j][0]=r[0]; bl[2*j][1]=r[2]; bl[2*j+1][0]=r[1]; bl[2*j+1][1]=r[3];
            }
            #pragma unroll
            for (int mt = 0; mt < 4; mt++){
                int row = wm + mt*16 + (lane & 15);
                int col = ks*16 + (lane >> 4)*8;
                ldsm4(ah[mt], As_hi + row*LDSH + col);
                ldsm4(al[mt], As_lo + row*LDSH + col);
            }
            #pragma unroll
            for (int mt = 0; mt < 4; mt++)
                #pragma unroll
                for (int nt = 0; nt < 4; nt++)
                    mma_bf16(acc[mt][nt], ah[mt], bh[nt]);
            #pragma unroll
            for (int mt = 0; mt < 4; mt++)
                #pragma unroll
                for (int nt = 0; nt < 4; nt++)
                    mma_bf16(acc[mt][nt], ah[mt], bl[nt]);
            #pragma unroll
            for (int mt = 0; mt < 4; mt++)
                #pragma unroll
                for (int nt = 0; nt < 4; nt++)
                    mma_bf16(acc[mt][nt], al[mt], bh[nt]);
        }
        __syncthreads();
    }

    // ---- epilogue ----
    #pragma unroll
    for (int mt = 0; mt < 4; mt++){
        #pragma unroll
        for (int nt = 0; nt < 4; nt++){
            int row0 = bm + wm + mt*16 + (lane >> 2);
            int col0 = bn + wn + nt*8 + 2*(lane & 3);
            #pragma unroll
            for (int f = 0; f < 4; f++){
                int gm = row0 + ((f >= 2) ? 8 : 0);
                int gn = col0 + (f & 1);
                if (gn < N){
                    float v = acc[mt][nt][f];
                    if (bias) v += bias[gn];
                    if (res)  v += res[(size_t)gm*N + gn];
                    if (doGelu) v = 0.5f*v*(1.0f + erff(v*0.70710678118654752f));
                    size_t o = (size_t)gm*N + gn;
                    if (Cf) Cf[o] = v;
                    if (Chi){
                        __nv_bfloat16 h, l;
                        split_bf16(v, h, l);
                        Chi[o] = h; Clo[o] = l;
                    }
                }
            }
        }
    }
}

// =====================================================================
// Flash-tiled causal attention.
// Block = (qtile of 64, head, batch); 128 threads; thread (q, half of 32 dims).
// Emits bf16 hi/lo planes for the proj GEMM.
// =====================================================================
#define FA_SMEM ((2*64*68 + 64*65)*4)

__global__ void __launch_bounds__(128) fattn_kernel(const float* __restrict__ qkv,
                                                    __nv_bfloat16* __restrict__ aoh,
                                                    __nv_bfloat16* __restrict__ aol){
    extern __shared__ float fs[];
    float* Ks = fs;                 // [64][68]
    float* Vs = fs + 64*68;         // [64][68]
    float* Ps = fs + 2*64*68;       // [64][65]

    int qt = blockIdx.x, hh = blockIdx.y, b = blockIdx.z;
    int tid = threadIdx.x;
    int q = tid >> 1, hf = tid & 1;
    int qg = qt*64 + q;
    const float* base = qkv + (size_t)b*TSZ*3*CSZ;

    // q registers (scaled)
    float qr[32];
    {
        const float* qp = base + (size_t)qg*3*CSZ + hh*192 + hf*32;
        #pragma unroll
        for (int i = 0; i < 8; i++){
            float4 v = *(const float4*)(qp + i*4);
            qr[i*4+0] = v.x*0.125f; qr[i*4+1] = v.y*0.125f;
            qr[i*4+2] = v.z*0.125f; qr[i*4+3] = v.w*0.125f;
        }
    }
    float o[32];
    #pragma unroll
    for (int i = 0; i < 32; i++) o[i] = 0.0f;
    float m = -1e30f, l = 0.0f;

    for (int st = 0; st <= qt; st++){
        int s0 = st*64;
        __syncthreads();   // protect prior tile use
        #pragma unroll
        for (int i = 0; i < 8; i++){
            int idx = tid + i*128;
            int r = idx >> 4, ch = idx & 15;
            const float* kp = base + (size_t)(s0+r)*3*CSZ + hh*192 + 64 + ch*4;
            *(float4*)&Ks[r*68 + ch*4] = *(const float4*)kp;
            *(float4*)&Vs[r*68 + ch*4] = *(const float4*)(kp + 64);
        }
        __syncthreads();

        bool diag = (st == qt);
        float mt_ = -1e30f;
        #pragma unroll 4
        for (int s = 0; s < 64; s++){
            const float* kr = &Ks[s*68 + hf*32];
            float p = 0.0f;
            #pragma unroll
            for (int i = 0; i < 8; i++){
                float4 kv = *(const float4*)(kr + i*4);
                p = fmaf(qr[i*4+0], kv.x, p);
                p = fmaf(qr[i*4+1], kv.y, p);
                p = fmaf(qr[i*4+2], kv.z, p);
                p = fmaf(qr[i*4+3], kv.w, p);
            }
            p += __shfl_xor_sync(0xffffffffu, p, 1);
            if (diag && (s0 + s) > qg) p = -1e30f;
            if (hf == 0) Ps[q*65 + s] = p;
            mt_ = fmaxf(mt_, p);
        }
        float mn = fmaxf(m, mt_);
        float sc = __expf(m - mn);
        l *= sc;
        #pragma unroll
        for (int i = 0; i < 32; i++) o[i] *= sc;
        m = mn;
        __syncwarp();
        #pragma unroll 4
        for (int s = 0; s < 64; s++){
            float e = __expf(Ps[q*65 + s] - m);
            l += e;
            const float* vr = &Vs[s*68 + hf*32];
            #pragma unroll
            for (int i = 0; i < 8; i++){
                float4 vv = *(const float4*)(vr + i*4);
                o[i*4+0] = fmaf(e, vv.x, o[i*4+0]);
                o[i*4+1] = fmaf(e, vv.y, o[i*4+1]);
                o[i*4+2] = fmaf(e, vv.z, o[i*4+2]);
                o[i*4+3] = fmaf(e, vv.w, o[i*4+3]);
            }
        }
    }

    float inv = 1.0f / l;
    size_t ob = ((size_t)(b*TSZ + qg))*CSZ + hh*64 + hf*32;
    #pragma unroll
    for (int i = 0; i < 32; i++){
        float v = o[i]*inv;
        __nv_bfloat16 h, lo;
        split_bf16(v, h, lo);
        aoh[ob + i] = h;
        aol[ob + i] = lo;
    }
}

// ---------------- launch ----------------
extern "C" void kernel_launch(void* const* d_in, const int* in_sizes, int n_in,
                              void* d_out, int out_size)
{
    const int*   idx    = (const int*)  d_in[0];
    const float* wte    = (const float*)d_in[1];
    const float* wpe    = (const float*)d_in[2];
    const float* ln1_g  = (const float*)d_in[3];
    const float* ln1_b  = (const float*)d_in[4];
    const float* attn_w = (const float*)d_in[5];
    const float* attn_b = (const float*)d_in[6];
    const float* proj_w = (const float*)d_in[7];
    const float* proj_b = (const float*)d_in[8];
    const float* ln2_g  = (const float*)d_in[9];
    const float* ln2_b  = (const float*)d_in[10];
    const float* fc_w   = (const float*)d_in[11];
    const float* fc_b   = (const float*)d_in[12];
    const float* fp_w   = (const float*)d_in[13];
    const float* fp_b   = (const float*)d_in[14];
    const float* lnf_g  = (const float*)d_in[15];
    const float* lnf_b  = (const float*)d_in[16];
    float* out = (float*)d_out;

    float *x, *qkv;
    cudaGetSymbolAddress((void**)&x,   g_x);
    cudaGetSymbolAddress((void**)&qkv, g_qkv);
    __nv_bfloat16 *hH, *hL, *aoH, *aoL, *hidH, *hidL;
    cudaGetSymbolAddress((void**)&hH,   g_h_hi);
    cudaGetSymbolAddress((void**)&hL,   g_h_lo);
    cudaGetSymbolAddress((void**)&aoH,  g_ao_hi);
    cudaGetSymbolAddress((void**)&aoL,  g_ao_lo);
    cudaGetSymbolAddress((void**)&hidH, g_hid_hi);
    cudaGetSymbolAddress((void**)&hidL, g_hid_lo);
    __nv_bfloat16 *atH, *atL, *prH, *prL, *fcH, *fcL, *fpH, *fpL, *wtH, *wtL;
    cudaGetSymbolAddress((void**)&atH, g_attnT_hi);
    cudaGetSymbolAddress((void**)&atL, g_attnT_lo);
    cudaGetSymbolAddress((void**)&prH, g_projT_hi);
    cudaGetSymbolAddress((void**)&prL, g_projT_lo);
    cudaGetSymbolAddress((void**)&fcH, g_fcT_hi);
    cudaGetSymbolAddress((void**)&fcL, g_fcT_lo);
    cudaGetSymbolAddress((void**)&fpH, g_fpT_hi);
    cudaGetSymbolAddress((void**)&fpL, g_fpT_lo);
    cudaGetSymbolAddress((void**)&wtH, g_wte_hi);
    cudaGetSymbolAddress((void**)&wtL, g_wte_lo);

    cudaFuncSetAttribute(gemm2, cudaFuncAttributeMaxDynamicSharedMemorySize, GSMEM);
    cudaFuncSetAttribute(fattn_kernel, cudaFuncAttributeMaxDynamicSharedMemorySize, FA_SMEM);

    // ---- weight conversion (deterministic each call) ----
    dim3 tb(32, 8);
    transcvt_kernel<<<dim3(3*CSZ/32, CSZ/32, LSZ), tb>>>(attn_w, atH, atL, CSZ, 3*CSZ);
    transcvt_kernel<<<dim3(CSZ/32, CSZ/32, LSZ), tb>>>(proj_w, prH, prL, CSZ, CSZ);
    transcvt_kernel<<<dim3(4*CSZ/32, CSZ/32, LSZ), tb>>>(fc_w, fcH, fcL, CSZ, 4*CSZ);
    transcvt_kernel<<<dim3(CSZ/32, 4*CSZ/32, LSZ), tb>>>(fp_w, fpH, fpL, 4*CSZ, CSZ);
    cvt_kernel<<<(VSZ*CSZ + 255)/256, 256>>>(wte, wtH, wtL, VSZ*CSZ);

    embed_kernel<<<(BT*CSZ + 255)/256, 256>>>(idx, wte, wpe, x);

    for (int l = 0; l < LSZ; l++){
        size_t oA = (size_t)l*3*CSZ*CSZ, oP = (size_t)l*CSZ*CSZ;
        size_t oF = (size_t)l*4*CSZ*CSZ;
        // attention
        ln_kernel<<<BT, 256>>>(x, ln1_g + (size_t)l*CSZ, ln1_b + (size_t)l*CSZ, hH, hL);
        gemm2<<<dim3(3*CSZ/128, BT/128), 256, GSMEM>>>(
            hH, hL, atH + oA, atL + oA, attn_b + (size_t)l*3*CSZ,
            nullptr, qkv, nullptr, nullptr, BT, 3*CSZ, CSZ, 0);
        fattn_kernel<<<dim3(TSZ/64, HSZ, BSZ), 128, FA_SMEM>>>(qkv, aoH, aoL);
        gemm2<<<dim3(CSZ/128, BT/128), 256, GSMEM>>>(
            aoH, aoL, prH + oP, prL + oP, proj_b + (size_t)l*CSZ,
            x, x, nullptr, nullptr, BT, CSZ, CSZ, 0);
        // MLP
        ln_kernel<<<BT, 256>>>(x, ln2_g + (size_t)l*CSZ, ln2_b + (size_t)l*CSZ, hH, hL);
        gemm2<<<dim3(4*CSZ/128, BT/128), 256, GSMEM>>>(
            hH, hL, fcH + oF, fcL + oF, fc_b + (size_t)l*4*CSZ,
            nullptr, nullptr, hidH, hidL, BT, 4*CSZ, CSZ, 1);
        gemm2<<<dim3(CSZ/128, BT/128), 256, GSMEM>>>(
            hidH, hidL, fpH + oF, fpL + oF, fp_b + (size_t)l*CSZ,
            x, x, nullptr, nullptr, BT, CSZ, 4*CSZ, 0);
    }

    // final LN + tied-embedding logits head
    ln_kernel<<<BT, 256>>>(x, lnf_g, lnf_b, hH, hL);
    gemm2<<<dim3((VSZ + 127)/128, BT/128), 256, GSMEM>>>(
        hH, hL, wtH, wtL, nullptr, nullptr, out, nullptr, nullptr, BT, VSZ, CSZ, 0);
}

// round 16
// speedup vs baseline: 3.4920x; 1.0226x over previous
#include <cuda_runtime.h>
#include <cuda_bf16.h>
#include <math.h>
#include <stdint.h>

// ---------------- problem constants ----------------
#define BSZ 2
#define TSZ 1024
#define CSZ 768
#define LSZ 12
#define HSZ 12
#define HDSZ 64
#define VSZ 50257
#define BT (BSZ*TSZ)

// ---------------- device scratch (no allocation allowed) ----------------
__device__ float g_x  [BT*CSZ];        // residual stream (fp32)
__device__ float g_qkv[BT*3*CSZ];      // qkv projection (fp32)
__device__ __nv_bfloat16 g_h_hi [BT*CSZ],   g_h_lo [BT*CSZ];    // ln out planes
__device__ __nv_bfloat16 g_ao_hi[BT*CSZ],   g_ao_lo[BT*CSZ];    // attn out planes
__device__ __nv_bfloat16 g_hid_hi[BT*4*CSZ], g_hid_lo[BT*4*CSZ];// MLP hidden planes

// pre-transposed/converted weights: [N][K] K-major bf16, hi & lo planes
__device__ __nv_bfloat16 g_attnT_hi[LSZ*3*CSZ*CSZ];
__device__ __nv_bfloat16 g_attnT_lo[LSZ*3*CSZ*CSZ];
__device__ __nv_bfloat16 g_projT_hi[LSZ*CSZ*CSZ];
__device__ __nv_bfloat16 g_projT_lo[LSZ*CSZ*CSZ];
__device__ __nv_bfloat16 g_fcT_hi  [LSZ*4*CSZ*CSZ];
__device__ __nv_bfloat16 g_fcT_lo  [LSZ*4*CSZ*CSZ];
__device__ __nv_bfloat16 g_fpT_hi  [LSZ*CSZ*4*CSZ];
__device__ __nv_bfloat16 g_fpT_lo  [LSZ*CSZ*4*CSZ];
__device__ __nv_bfloat16 g_wte_hi  [VSZ*CSZ];
__device__ __nv_bfloat16 g_wte_lo  [VSZ*CSZ];

// ---------------- small helpers ----------------
__device__ __forceinline__ float warpReduceSum(float v){
    #pragma unroll
    for (int o = 16; o > 0; o >>= 1) v += __shfl_xor_sync(0xffffffffu, v, o);
    return v;
}
__device__ __forceinline__ float blockReduceSum(float v, float* sh){
    int lane = threadIdx.x & 31, w = threadIdx.x >> 5;
    v = warpReduceSum(v);
    __syncthreads();
    if (lane == 0) sh[w] = v;
    __syncthreads();
    int nw = blockDim.x >> 5;
    float r = (threadIdx.x < nw) ? sh[threadIdx.x] : 0.0f;
    if (w == 0){ r = warpReduceSum(r); if (lane == 0) sh[0] = r; }
    __syncthreads();
    return sh[0];
}
__device__ __forceinline__ void split_bf16(float v, __nv_bfloat16& h, __nv_bfloat16& l){
    h = __float2bfloat16(v);
    l = __float2bfloat16(v - __bfloat162float(h));
}

// =====================================================================
// fused weight conversion: all 4 transposed weight groups + wte, 1 launch
// =====================================================================
#define NT_ATTN (72*24*LSZ)                       // 20736
#define NT_PROJ (NT_ATTN + 24*24*LSZ)             // 27648
#define NT_FC   (NT_PROJ + 96*24*LSZ)             // 55296
#define NT_FP   (NT_FC   + 24*96*LSZ)             // 82944
#define WTE_BLKS ((VSZ*CSZ + 8191)/8192)          // 4713
#define NT_ALL  (NT_FP + WTE_BLKS)

__device__ __forceinline__ void transcvt_tile(float (*t)[33],
    const float* __restrict__ Wl, __nv_bfloat16* __restrict__ Hl,
    __nv_bfloat16* __restrict__ Ll, int K, int N, int k0, int n0,
    int tx, int ty)
{
    #pragma unroll
    for (int i = ty; i < 32; i += 8)
        t[i][tx] = Wl[(size_t)(k0+i)*N + n0 + tx];
    __syncthreads();
    #pragma unroll
    for (int i = ty; i < 32; i += 8){
        float v = t[tx][i];                      // W[k0+tx][n0+i]
        __nv_bfloat16 h, lo;
        split_bf16(v, h, lo);
        Hl[(size_t)(n0+i)*K + k0 + tx] = h;
        Ll[(size_t)(n0+i)*K + k0 + tx] = lo;
    }
}

__global__ void __launch_bounds__(256) convw_kernel(
    const float* __restrict__ attn_w, const float* __restrict__ proj_w,
    const float* __restrict__ fc_w,   const float* __restrict__ fp_w,
    const float* __restrict__ wte,
    __nv_bfloat16* atH, __nv_bfloat16* atL, __nv_bfloat16* prH, __nv_bfloat16* prL,
    __nv_bfloat16* fcH, __nv_bfloat16* fcL, __nv_bfloat16* fpH, __nv_bfloat16* fpL,
    __nv_bfloat16* wtH, __nv_bfloat16* wtL)
{
    __shared__ float t[32][33];
    int bid = blockIdx.x;
    int tx = threadIdx.x & 31, ty = threadIdx.x >> 5;

    if (bid < NT_ATTN){
        int rel = bid, per = 72*24;
        int l = rel / per, r = rel % per, tn = r % 72, tk = r / 72;
        size_t o = (size_t)l*CSZ*3*CSZ;
        transcvt_tile(t, attn_w + o, atH + o, atL + o, CSZ, 3*CSZ, tk*32, tn*32, tx, ty);
    } else if (bid < NT_PROJ){
        int rel = bid - NT_ATTN, per = 24*24;
        int l = rel / per, r = rel % per, tn = r % 24, tk = r / 24;
        size_t o = (size_t)l*CSZ*CSZ;
        transcvt_tile(t, proj_w + o, prH + o, prL + o, CSZ, CSZ, tk*32, tn*32, tx, ty);
    } else if (bid < NT_FC){
        int rel = bid - NT_PROJ, per = 96*24;
        int l = rel / per, r = rel % per, tn = r % 96, tk = r / 96;
        size_t o = (size_t)l*CSZ*4*CSZ;
        transcvt_tile(t, fc_w + o, fcH + o, fcL + o, CSZ, 4*CSZ, tk*32, tn*32, tx, ty);
    } else if (bid < NT_FP){
        int rel = bid - NT_FC, per = 24*96;
        int l = rel / per, r = rel % per, tn = r % 24, tk = r / 24;
        size_t o = (size_t)l*4*CSZ*CSZ;
        transcvt_tile(t, fp_w + o, fpH + o, fpL + o, 4*CSZ, CSZ, tk*32, tn*32, tx, ty);
    } else {
        int base = (bid - NT_FP)*8192 + ty*32 + tx;
        #pragma unroll
        for (int i = 0; i < 32; i++){
            int idx = base + i*256;
            if (idx < VSZ*CSZ){
                __nv_bfloat16 h, l;
                split_bf16(wte[idx], h, l);
                wtH[idx] = h; wtL[idx] = l;
            }
        }
    }
}

// ---------------- embedding ----------------
__global__ void embed_kernel(const int* __restrict__ idx,
                             const float* __restrict__ wte,
                             const float* __restrict__ wpe,
                             float* __restrict__ x){
    int i = blockIdx.x * blockDim.x + threadIdx.x;
    if (i >= BT*CSZ) return;
    int c  = i % CSZ;
    int bt = i / CSZ;
    int t  = bt % TSZ;
    x[i] = wte[(size_t)idx[bt]*CSZ + c] + wpe[(size_t)t*CSZ + c];
}

// ---------------- layernorm -> bf16 hi/lo planes ----------------
__global__ void __launch_bounds__(256) ln_kernel(const float* __restrict__ x,
                                                 const float* __restrict__ g,
                                                 const float* __restrict__ b,
                                                 __nv_bfloat16* __restrict__ oh,
                                                 __nv_bfloat16* __restrict__ ol){
    __shared__ float sh[32];
    int row = blockIdx.x, tid = threadIdx.x;
    const float* xr = x + (size_t)row*CSZ;
    float v0 = xr[tid], v1 = xr[tid+256], v2 = xr[tid+512];
    float mean = blockReduceSum(v0+v1+v2, sh) * (1.0f/CSZ);
    float d0 = v0-mean, d1 = v1-mean, d2 = v2-mean;
    float var = blockReduceSum(d0*d0 + d1*d1 + d2*d2, sh) * (1.0f/CSZ);
    float rs = rsqrtf(var + 1e-5f);
    size_t base = (size_t)row*CSZ;
    #pragma unroll
    for (int j = 0; j < 3; j++){
        int c = tid + j*256;
        float d = (j==0)?d0:((j==1)?d1:d2);
        float val = d*rs*g[c] + b[c];
        __nv_bfloat16 h, l;
        split_bf16(val, h, l);
        oh[base + c] = h;
        ol[base + c] = l;
    }
}

// =====================================================================
// bf16 split GEMM, cp.async double-buffered, tile BMTx128x32.
// C[M,N] = A[M,K] @ B^T ; A planes [M][K], B planes [N][K], all K-major bf16.
// 3 terms: hiA*hiB + hiA*loB + loA*hiB, fp32 accumulate.
// M%BMT==0, K%32==0, N guarded.
// =====================================================================
#define LDSH 40                       // halves per smem row (80 bytes)
#define BPLANE 10240                  // 128 rows * 80B

__device__ __forceinline__ void ldsm4(uint32_t* r, const __nv_bfloat16* p){
    uint32_t addr = (uint32_t)__cvta_generic_to_shared(p);
    asm volatile("ldmatrix.sync.aligned.m8n8.x4.shared.b16 {%0,%1,%2,%3}, [%4];"
        : "=r"(r[0]), "=r"(r[1]), "=r"(r[2]), "=r"(r[3]) : "r"(addr));
}
__device__ __forceinline__ void mma_bf16(float* c, const uint32_t* a, const uint32_t* b){
    asm("mma.sync.aligned.m16n8k16.row.col.f32.bf16.bf16.f32 "
        "{%0,%1,%2,%3}, {%4,%5,%6,%7}, {%8,%9}, {%0,%1,%2,%3};\n"
        : "+f"(c[0]), "+f"(c[1]), "+f"(c[2]), "+f"(c[3])
        : "r"(a[0]), "r"(a[1]), "r"(a[2]), "r"(a[3]), "r"(b[0]), "r"(b[1]));
}
__device__ __forceinline__ void cp16(uint32_t dst, const void* src, bool pred){
    int sz = pred ? 16 : 0;
    asm volatile("cp.async.cg.shared.global [%0], [%1], 16, %2;\n"
        :: "r"(dst), "l"(src), "r"(sz));
}
__device__ __forceinline__ void cp_commit(){
    asm volatile("cp.async.commit_group;\n" ::: "memory");
}
template<int NW> __device__ __forceinline__ void cp_wait(){
    asm volatile("cp.async.wait_group %0;\n" :: "n"(NW) : "memory");
}

template<int BMT>
__device__ __forceinline__ void fill_stage(uint32_t s0,
    const __nv_bfloat16* Ahi, const __nv_bfloat16* Alo,
    const __nv_bfloat16* Bhi, const __nv_bfloat16* Blo,
    int bm, int bn, int k0, int K, int N, int tid)
{
    constexpr int APLANE = BMT*80;
    constexpr int ACH = 2*BMT*4;
    constexpr int TCH = ACH + 2*128*4;
    #pragma unroll
    for (int i = 0; i < TCH/256; i++){
        int idx = tid + i*256;
        if (idx < ACH){
            int plane = idx / (BMT*4);
            int r = (idx >> 2) % BMT;
            int ch = idx & 3;
            uint32_t dst = s0 + plane*APLANE + r*80 + ch*16;
            const __nv_bfloat16* base = plane ? Alo : Ahi;
            cp16(dst, base + (size_t)(bm + r)*K + k0 + ch*8, true);
        } else {
            int j = idx - ACH;
            int plane = j >> 9;
            int r = (j >> 2) & 127;
            int ch = j & 3;
            uint32_t dst = s0 + 2*APLANE + plane*BPLANE + r*80 + ch*16;
            const __nv_bfloat16* base = plane ? Blo : Bhi;
            int gn = bn + r;
            cp16(dst, base + (size_t)gn*K + k0 + ch*8, gn < N);
        }
    }
}

template<int BMT>
__global__ void __launch_bounds__(256) gemm2(
    const __nv_bfloat16* __restrict__ Ahi, const __nv_bfloat16* __restrict__ Alo,
    const __nv_bfloat16* __restrict__ Bhi, const __nv_bfloat16* __restrict__ Blo,
    const float* __restrict__ bias, const float* __restrict__ res,
    float* __restrict__ Cf, __nv_bfloat16* __restrict__ Chi, __nv_bfloat16* __restrict__ Clo,
    int M, int N, int K, int doGelu)
{
    constexpr int APLANE = BMT*80;
    constexpr int STAGE = 2*APLANE + 2*BPLANE;
    constexpr int MT = BMT/32;        // 16-row m-tiles per warp

    extern __shared__ char smem[];
    uint32_t sb = (uint32_t)__cvta_generic_to_shared(smem);
    int tid = threadIdx.x, lane = tid & 31, warp = tid >> 5;
    int bm = blockIdx.y * BMT, bn = blockIdx.x * 128;
    int wm = (warp >> 2) * (BMT/2);   // warp grid 2(m) x 4(n)
    int wn = (warp & 3) * 32;

    float acc[MT][4][4];
    #pragma unroll
    for (int i = 0; i < MT; i++)
        #pragma unroll
        for (int j = 0; j < 4; j++)
            #pragma unroll
            for (int f = 0; f < 4; f++) acc[i][j][f] = 0.0f;

    int niter = K / 32;
    fill_stage<BMT>(sb, Ahi, Alo, Bhi, Blo, bm, bn, 0, K, N, tid);
    cp_commit();

    for (int it = 0; it < niter; it++){
        if (it + 1 < niter){
            fill_stage<BMT>(sb + ((it+1)&1)*STAGE, Ahi, Alo, Bhi, Blo,
                            bm, bn, (it+1)*32, K, N, tid);
            cp_commit();
            cp_wait<1>();
        } else {
            cp_wait<0>();
        }
        __syncthreads();

        const char* st = smem + (it & 1)*STAGE;
        const __nv_bfloat16* As_hi = (const __nv_bfloat16*)(st);
        const __nv_bfloat16* As_lo = (const __nv_bfloat16*)(st + APLANE);
        const __nv_bfloat16* Bs_hi = (const __nv_bfloat16*)(st + 2*APLANE);
        const __nv_bfloat16* Bs_lo = (const __nv_bfloat16*)(st + 2*APLANE + BPLANE);

        #pragma unroll
        for (int ks = 0; ks < 2; ks++){
            uint32_t ah[MT][4], al[MT][4], bh[4][2], bl[4][2];
            #pragma unroll
            for (int j = 0; j < 2; j++){
                uint32_t r[4];
                int row = wn + j*16 + (lane & 15);
                int col = ks*16 + (lane >> 4)*8;
                ldsm4(r, Bs_hi + row*LDSH + col);
                bh[2*j][0]=r[0]; bh[2*j][1]=r[2]; bh[2*j+1][0]=r[1]; bh[2*j+1][1]=r[3];
                ldsm4(r, Bs_lo + row*LDSH + col);
                bl[2*j][0]=r[0]; bl[2*j][1]=r[2]; bl[2*j+1][0]=r[1]; bl[2*j+1][1]=r[3];
            }
            #pragma unroll
            for (int mt = 0; mt < MT; mt++){
                int row = wm + mt*16 + (lane & 15);
                int col = ks*16 + (lane >> 4)*8;
                ldsm4(ah[mt], As_hi + row*LDSH + col);
                ldsm4(al[mt], As_lo + row*LDSH + col);
            }
            #pragma unroll
            for (int mt = 0; mt < MT; mt++)
                #pragma unroll
                for (int nt = 0; nt < 4; nt++)
                    mma_bf16(acc[mt][nt], ah[mt], bh[nt]);
            #pragma unroll
            for (int mt = 0; mt < MT; mt++)
                #pragma unroll
                for (int nt = 0; nt < 4; nt++)
                    mma_bf16(acc[mt][nt], ah[mt], bl[nt]);
            #pragma unroll
            for (int mt = 0; mt < MT; mt++)
                #pragma unroll
                for (int nt = 0; nt < 4; nt++)
                    mma_bf16(acc[mt][nt], al[mt], bh[nt]);
        }
        __syncthreads();
    }

    // ---- epilogue ----
    #pragma unroll
    for (int mt = 0; mt < MT; mt++){
        #pragma unroll
        for (int nt = 0; nt < 4; nt++){
            int row0 = bm + wm + mt*16 + (lane >> 2);
            int col0 = bn + wn + nt*8 + 2*(lane & 3);
            #pragma unroll
            for (int f = 0; f < 4; f++){
                int gm = row0 + ((f >= 2) ? 8 : 0);
                int gn = col0 + (f & 1);
                if (gn < N){
                    float v = acc[mt][nt][f];
                    if (bias) v += bias[gn];
                    if (res)  v += res[(size_t)gm*N + gn];
                    if (doGelu) v = 0.5f*v*(1.0f + erff(v*0.70710678118654752f));
                    size_t o = (size_t)gm*N + gn;
                    if (Cf) Cf[o] = v;
                    if (Chi){
                        __nv_bfloat16 h, l;
                        split_bf16(v, h, l);
                        Chi[o] = h; Clo[o] = l;
                    }
                }
            }
        }
    }
}

// =====================================================================
// Flash-tiled causal attention (as R15 — verified fast & correct)
// =====================================================================
#define FA_SMEM ((2*64*68 + 64*65)*4)

__global__ void __launch_bounds__(128) fattn_kernel(const float* __restrict__ qkv,
                                                    __nv_bfloat16* __restrict__ aoh,
                                                    __nv_bfloat16* __restrict__ aol){
    extern __shared__ float fs[];
    float* Ks = fs;                 // [64][68]
    float* Vs = fs + 64*68;         // [64][68]
    float* Ps = fs + 2*64*68;       // [64][65]

    int qt = blockIdx.x, hh = blockIdx.y, b = blockIdx.z;
    int tid = threadIdx.x;
    int q = tid >> 1, hf = tid & 1;
    int qg = qt*64 + q;
    const float* base = qkv + (size_t)b*TSZ*3*CSZ;

    float qr[32];
    {
        const float* qp = base + (size_t)qg*3*CSZ + hh*192 + hf*32;
        #pragma unroll
        for (int i = 0; i < 8; i++){
            float4 v = *(const float4*)(qp + i*4);
            qr[i*4+0] = v.x*0.125f; qr[i*4+1] = v.y*0.125f;
            qr[i*4+2] = v.z*0.125f; qr[i*4+3] = v.w*0.125f;
        }
    }
    float o[32];
    #pragma unroll
    for (int i = 0; i < 32; i++) o[i] = 0.0f;
    float m = -1e30f, l = 0.0f;

    for (int st = 0; st <= qt; st++){
        int s0 = st*64;
        __syncthreads();
        #pragma unroll
        for (int i = 0; i < 8; i++){
            int idx = tid + i*128;
            int r = idx >> 4, ch = idx & 15;
            const float* kp = base + (size_t)(s0+r)*3*CSZ + hh*192 + 64 + ch*4;
            *(float4*)&Ks[r*68 + ch*4] = *(const float4*)kp;
            *(float4*)&Vs[r*68 + ch*4] = *(const float4*)(kp + 64);
        }
        __syncthreads();

        bool diag = (st == qt);
        float mt_ = -1e30f;
        #pragma unroll 4
        for (int s = 0; s < 64; s++){
            const float* kr = &Ks[s*68 + hf*32];
            float p = 0.0f;
            #pragma unroll
            for (int i = 0; i < 8; i++){
                float4 kv = *(const float4*)(kr + i*4);
                p = fmaf(qr[i*4+0], kv.x, p);
                p = fmaf(qr[i*4+1], kv.y, p);
                p = fmaf(qr[i*4+2], kv.z, p);
                p = fmaf(qr[i*4+3], kv.w, p);
            }
            p += __shfl_xor_sync(0xffffffffu, p, 1);
            if (diag && (s0 + s) > qg) p = -1e30f;
            if (hf == 0) Ps[q*65 + s] = p;
            mt_ = fmaxf(mt_, p);
        }
        float mn = fmaxf(m, mt_);
        float sc = __expf(m - mn);
        l *= sc;
        #pragma unroll
        for (int i = 0; i < 32; i++) o[i] *= sc;
        m = mn;
        __syncwarp();
        #pragma unroll 4
        for (int s = 0; s < 64; s++){
            float e = __expf(Ps[q*65 + s] - m);
            l += e;
            const float* vr = &Vs[s*68 + hf*32];
            #pragma unroll
            for (int i = 0; i < 8; i++){
                float4 vv = *(const float4*)(vr + i*4);
                o[i*4+0] = fmaf(e, vv.x, o[i*4+0]);
                o[i*4+1] = fmaf(e, vv.y, o[i*4+1]);
                o[i*4+2] = fmaf(e, vv.z, o[i*4+2]);
                o[i*4+3] = fmaf(e, vv.w, o[i*4+3]);
            }
        }
    }

    float inv = 1.0f / l;
    size_t ob = ((size_t)(b*TSZ + qg))*CSZ + hh*64 + hf*32;
    #pragma unroll
    for (int i = 0; i < 32; i++){
        float v = o[i]*inv;
        __nv_bfloat16 h, lo;
        split_bf16(v, h, lo);
        aoh[ob + i] = h;
        aol[ob + i] = lo;
    }
}

// ---------------- launch ----------------
extern "C" void kernel_launch(void* const* d_in, const int* in_sizes, int n_in,
                              void* d_out, int out_size)
{
    const int*   idx    = (const int*)  d_in[0];
    const float* wte    = (const float*)d_in[1];
    const float* wpe    = (const float*)d_in[2];
    const float* ln1_g  = (const float*)d_in[3];
    const float* ln1_b  = (const float*)d_in[4];
    const float* attn_w = (const float*)d_in[5];
    const float* attn_b = (const float*)d_in[6];
    const float* proj_w = (const float*)d_in[7];
    const float* proj_b = (const float*)d_in[8];
    const float* ln2_g  = (const float*)d_in[9];
    const float* ln2_b  = (const float*)d_in[10];
    const float* fc_w   = (const float*)d_in[11];
    const float* fc_b   = (const float*)d_in[12];
    const float* fp_w   = (const float*)d_in[13];
    const float* fp_b   = (const float*)d_in[14];
    const float* lnf_g  = (const float*)d_in[15];
    const float* lnf_b  = (const float*)d_in[16];
    float* out = (float*)d_out;

    float *x, *qkv;
    cudaGetSymbolAddress((void**)&x,   g_x);
    cudaGetSymbolAddress((void**)&qkv, g_qkv);
    __nv_bfloat16 *hH, *hL, *aoH, *aoL, *hidH, *hidL;
    cudaGetSymbolAddress((void**)&hH,   g_h_hi);
    cudaGetSymbolAddress((void**)&hL,   g_h_lo);
    cudaGetSymbolAddress((void**)&aoH,  g_ao_hi);
    cudaGetSymbolAddress((void**)&aoL,  g_ao_lo);
    cudaGetSymbolAddress((void**)&hidH, g_hid_hi);
    cudaGetSymbolAddress((void**)&hidL, g_hid_lo);
    __nv_bfloat16 *atH, *atL, *prH, *prL, *fcH, *fcL, *fpH, *fpL, *wtH, *wtL;
    cudaGetSymbolAddress((void**)&atH, g_attnT_hi);
    cudaGetSymbolAddress((void**)&atL, g_attnT_lo);
    cudaGetSymbolAddress((void**)&prH, g_projT_hi);
    cudaGetSymbolAddress((void**)&prL, g_projT_lo);
    cudaGetSymbolAddress((void**)&fcH, g_fcT_hi);
    cudaGetSymbolAddress((void**)&fcL, g_fcT_lo);
    cudaGetSymbolAddress((void**)&fpH, g_fpT_hi);
    cudaGetSymbolAddress((void**)&fpL, g_fpT_lo);
    cudaGetSymbolAddress((void**)&wtH, g_wte_hi);
    cudaGetSymbolAddress((void**)&wtL, g_wte_lo);

    const int GS128 = 2*(2*128*80 + 2*BPLANE);   // 81920
    const int GS64  = 2*(2*64*80  + 2*BPLANE);   // 61440
    cudaFuncSetAttribute(gemm2<128>, cudaFuncAttributeMaxDynamicSharedMemorySize, GS128);
    cudaFuncSetAttribute(gemm2<64>,  cudaFuncAttributeMaxDynamicSharedMemorySize, GS64);
    cudaFuncSetAttribute(fattn_kernel, cudaFuncAttributeMaxDynamicSharedMemorySize, FA_SMEM);

    // 1: fused weight conversion (single launch)
    convw_kernel<<<NT_ALL, 256>>>(attn_w, proj_w, fc_w, fp_w, wte,
                                  atH, atL, prH, prL, fcH, fcL, fpH, fpL, wtH, wtL);
    // 2: embedding
    embed_kernel<<<(BT*CSZ + 255)/256, 256>>>(idx, wte, wpe, x);

    for (int l = 0; l < LSZ; l++){
        size_t oA = (size_t)l*3*CSZ*CSZ, oP = (size_t)l*CSZ*CSZ;
        size_t oF = (size_t)l*4*CSZ*CSZ;
        // attention
        ln_kernel<<<BT, 256>>>(x, ln1_g + (size_t)l*CSZ, ln1_b + (size_t)l*CSZ, hH, hL);
        gemm2<128><<<dim3(3*CSZ/128, BT/128), 256, GS128>>>(
            hH, hL, atH + oA, atL + oA, attn_b + (size_t)l*3*CSZ,
            nullptr, qkv, nullptr, nullptr, BT, 3*CSZ, CSZ, 0);
        fattn_kernel<<<dim3(TSZ/64, HSZ, BSZ), 128, FA_SMEM>>>(qkv, aoH, aoL);
        gemm2<64><<<dim3(CSZ/128, BT/64), 256, GS64>>>(
            aoH, aoL, prH + oP, prL + oP, proj_b + (size_t)l*CSZ,
            x, x, nullptr, nullptr, BT, CSZ, CSZ, 0);
        // MLP
        ln_kernel<<<BT, 256>>>(x, ln2_g + (size_t)l*CSZ, ln2_b + (size_t)l*CSZ, hH, hL);
        gemm2<128><<<dim3(4*CSZ/128, BT/128), 256, GS128>>>(
            hH, hL, fcH + oF, fcL + oF, fc_b + (size_t)l*4*CSZ,
            nullptr, nullptr, hidH, hidL, BT, 4*CSZ, CSZ, 1);
        gemm2<64><<<dim3(CSZ/128, BT/64), 256, GS64>>>(
            hidH, hidL, fpH + oF, fpL + oF, fp_b + (size_t)l*CSZ,
            x, x, nullptr, nullptr, BT, CSZ, 4*CSZ, 0);
    }

    // final LN + tied-embedding logits head
    ln_kernel<<<BT, 256>>>(x, lnf_g, lnf_b, hH, hL);
    gemm2<128><<<dim3((VSZ + 127)/128, BT/128), 256, GS128>>>(
        hH, hL, wtH, wtL, nullptr, nullptr, out, nullptr, nullptr, BT, VSZ, CSZ, 0);
}

// round 17
// speedup vs baseline: 3.5222x; 1.0087x over previous
#include <cuda_runtime.h>
#include <cuda_bf16.h>
#include <math.h>
#include <stdint.h>

// ---------------- problem constants ----------------
#define BSZ 2
#define TSZ 1024
#define CSZ 768
#define LSZ 12
#define HSZ 12
#define HDSZ 64
#define VSZ 50257
#define BT (BSZ*TSZ)

// ---------------- device scratch (no allocation allowed) ----------------
__device__ float g_x  [BT*CSZ];        // residual stream (fp32)
__device__ float g_qkv[BT*3*CSZ];      // qkv projection (fp32)
__device__ __nv_bfloat16 g_h_hi [BT*CSZ],   g_h_lo [BT*CSZ];    // ln out planes
__device__ __nv_bfloat16 g_ao_hi[BT*CSZ],   g_ao_lo[BT*CSZ];    // attn out planes
__device__ __nv_bfloat16 g_hid_hi[BT*4*CSZ], g_hid_lo[BT*4*CSZ];// MLP hidden planes

// pre-transposed/converted weights: [N][K] K-major bf16, hi & lo planes
__device__ __nv_bfloat16 g_attnT_hi[LSZ*3*CSZ*CSZ];
__device__ __nv_bfloat16 g_attnT_lo[LSZ*3*CSZ*CSZ];
__device__ __nv_bfloat16 g_projT_hi[LSZ*CSZ*CSZ];
__device__ __nv_bfloat16 g_projT_lo[LSZ*CSZ*CSZ];
__device__ __nv_bfloat16 g_fcT_hi  [LSZ*4*CSZ*CSZ];
__device__ __nv_bfloat16 g_fcT_lo  [LSZ*4*CSZ*CSZ];
__device__ __nv_bfloat16 g_fpT_hi  [LSZ*CSZ*4*CSZ];
__device__ __nv_bfloat16 g_fpT_lo  [LSZ*CSZ*4*CSZ];
__device__ __nv_bfloat16 g_wte_hi  [VSZ*CSZ];
__device__ __nv_bfloat16 g_wte_lo  [VSZ*CSZ];

// ---------------- small helpers ----------------
__device__ __forceinline__ float warpReduceSum(float v){
    #pragma unroll
    for (int o = 16; o > 0; o >>= 1) v += __shfl_xor_sync(0xffffffffu, v, o);
    return v;
}
__device__ __forceinline__ float blockReduceSum(float v, float* sh){
    int lane = threadIdx.x & 31, w = threadIdx.x >> 5;
    v = warpReduceSum(v);
    __syncthreads();
    if (lane == 0) sh[w] = v;
    __syncthreads();
    int nw = blockDim.x >> 5;
    float r = (threadIdx.x < nw) ? sh[threadIdx.x] : 0.0f;
    if (w == 0){ r = warpReduceSum(r); if (lane == 0) sh[0] = r; }
    __syncthreads();
    return sh[0];
}
__device__ __forceinline__ void split_bf16(float v, __nv_bfloat16& h, __nv_bfloat16& l){
    h = __float2bfloat16(v);
    l = __float2bfloat16(v - __bfloat162float(h));
}

// =====================================================================
// fused weight conversion: all 4 transposed weight groups + wte, 1 launch
// =====================================================================
#define NT_ATTN (72*24*LSZ)                       // 20736
#define NT_PROJ (NT_ATTN + 24*24*LSZ)             // 27648
#define NT_FC   (NT_PROJ + 96*24*LSZ)             // 55296
#define NT_FP   (NT_FC   + 24*96*LSZ)             // 82944
#define WTE_BLKS ((VSZ*CSZ + 8191)/8192)          // 4713
#define NT_ALL  (NT_FP + WTE_BLKS)

__device__ __forceinline__ void transcvt_tile(float (*t)[33],
    const float* __restrict__ Wl, __nv_bfloat16* __restrict__ Hl,
    __nv_bfloat16* __restrict__ Ll, int K, int N, int k0, int n0,
    int tx, int ty)
{
    #pragma unroll
    for (int i = ty; i < 32; i += 8)
        t[i][tx] = Wl[(size_t)(k0+i)*N + n0 + tx];
    __syncthreads();
    #pragma unroll
    for (int i = ty; i < 32; i += 8){
        float v = t[tx][i];                      // W[k0+tx][n0+i]
        __nv_bfloat16 h, lo;
        split_bf16(v, h, lo);
        Hl[(size_t)(n0+i)*K + k0 + tx] = h;
        Ll[(size_t)(n0+i)*K + k0 + tx] = lo;
    }
}

__global__ void __launch_bounds__(256) convw_kernel(
    const float* __restrict__ attn_w, const float* __restrict__ proj_w,
    const float* __restrict__ fc_w,   const float* __restrict__ fp_w,
    const float* __restrict__ wte,
    __nv_bfloat16* atH, __nv_bfloat16* atL, __nv_bfloat16* prH, __nv_bfloat16* prL,
    __nv_bfloat16* fcH, __nv_bfloat16* fcL, __nv_bfloat16* fpH, __nv_bfloat16* fpL,
    __nv_bfloat16* wtH, __nv_bfloat16* wtL)
{
    __shared__ float t[32][33];
    int bid = blockIdx.x;
    int tx = threadIdx.x & 31, ty = threadIdx.x >> 5;

    if (bid < NT_ATTN){
        int rel = bid, per = 72*24;
        int l = rel / per, r = rel % per, tn = r % 72, tk = r / 72;
        size_t o = (size_t)l*CSZ*3*CSZ;
        transcvt_tile(t, attn_w + o, atH + o, atL + o, CSZ, 3*CSZ, tk*32, tn*32, tx, ty);
    } else if (bid < NT_PROJ){
        int rel = bid - NT_ATTN, per = 24*24;
        int l = rel / per, r = rel % per, tn = r % 24, tk = r / 24;
        size_t o = (size_t)l*CSZ*CSZ;
        transcvt_tile(t, proj_w + o, prH + o, prL + o, CSZ, CSZ, tk*32, tn*32, tx, ty);
    } else if (bid < NT_FC){
        int rel = bid - NT_PROJ, per = 96*24;
        int l = rel / per, r = rel % per, tn = r % 96, tk = r / 96;
        size_t o = (size_t)l*CSZ*4*CSZ;
        transcvt_tile(t, fc_w + o, fcH + o, fcL + o, CSZ, 4*CSZ, tk*32, tn*32, tx, ty);
    } else if (bid < NT_FP){
        int rel = bid - NT_FC, per = 24*96;
        int l = rel / per, r = rel % per, tn = r % 24, tk = r / 24;
        size_t o = (size_t)l*4*CSZ*CSZ;
        transcvt_tile(t, fp_w + o, fpH + o, fpL + o, 4*CSZ, CSZ, tk*32, tn*32, tx, ty);
    } else {
        int base = (bid - NT_FP)*8192 + ty*32 + tx;
        #pragma unroll
        for (int i = 0; i < 32; i++){
            int idx = base + i*256;
            if (idx < VSZ*CSZ){
                __nv_bfloat16 h, l;
                split_bf16(wte[idx], h, l);
                wtH[idx] = h; wtL[idx] = l;
            }
        }
    }
}

// ---------------- embedding ----------------
__global__ void embed_kernel(const int* __restrict__ idx,
                             const float* __restrict__ wte,
                             const float* __restrict__ wpe,
                             float* __restrict__ x){
    int i = blockIdx.x * blockDim.x + threadIdx.x;
    if (i >= BT*CSZ) return;
    int c  = i % CSZ;
    int bt = i / CSZ;
    int t  = bt % TSZ;
    x[i] = wte[(size_t)idx[bt]*CSZ + c] + wpe[(size_t)t*CSZ + c];
}

// ---------------- layernorm -> bf16 hi/lo planes ----------------
__global__ void __launch_bounds__(256) ln_kernel(const float* __restrict__ x,
                                                 const float* __restrict__ g,
                                                 const float* __restrict__ b,
                                                 __nv_bfloat16* __restrict__ oh,
                                                 __nv_bfloat16* __restrict__ ol){
    __shared__ float sh[32];
    int row = blockIdx.x, tid = threadIdx.x;
    const float* xr = x + (size_t)row*CSZ;
    float v0 = xr[tid], v1 = xr[tid+256], v2 = xr[tid+512];
    float mean = blockReduceSum(v0+v1+v2, sh) * (1.0f/CSZ);
    float d0 = v0-mean, d1 = v1-mean, d2 = v2-mean;
    float var = blockReduceSum(d0*d0 + d1*d1 + d2*d2, sh) * (1.0f/CSZ);
    float rs = rsqrtf(var + 1e-5f);
    size_t base = (size_t)row*CSZ;
    #pragma unroll
    for (int j = 0; j < 3; j++){
        int c = tid + j*256;
        float d = (j==0)?d0:((j==1)?d1:d2);
        float val = d*rs*g[c] + b[c];
        __nv_bfloat16 h, l;
        split_bf16(val, h, l);
        oh[base + c] = h;
        ol[base + c] = l;
    }
}

// =====================================================================
// bf16 split GEMM, cp.async 2-stage, ONE __syncthreads per iteration.
// C[M,N] = A[M,K] @ B^T ; A planes [M][K], B planes [N][K], K-major bf16.
// 3 terms: hiA*hiB + hiA*loB + loA*hiB, fp32 accumulate.
// Tile BMT x BNT x 32. M%BMT==0, K%32==0, N guarded.
// =====================================================================
#define LDSH 40                       // halves per smem row (80 bytes)

__device__ __forceinline__ void ldsm4(uint32_t* r, const __nv_bfloat16* p){
    uint32_t addr = (uint32_t)__cvta_generic_to_shared(p);
    asm volatile("ldmatrix.sync.aligned.m8n8.x4.shared.b16 {%0,%1,%2,%3}, [%4];"
        : "=r"(r[0]), "=r"(r[1]), "=r"(r[2]), "=r"(r[3]) : "r"(addr));
}
__device__ __forceinline__ void mma_bf16(float* c, const uint32_t* a, const uint32_t* b){
    asm("mma.sync.aligned.m16n8k16.row.col.f32.bf16.bf16.f32 "
        "{%0,%1,%2,%3}, {%4,%5,%6,%7}, {%8,%9}, {%0,%1,%2,%3};\n"
        : "+f"(c[0]), "+f"(c[1]), "+f"(c[2]), "+f"(c[3])
        : "r"(a[0]), "r"(a[1]), "r"(a[2]), "r"(a[3]), "r"(b[0]), "r"(b[1]));
}
__device__ __forceinline__ void cp16(uint32_t dst, const void* src, bool pred){
    int sz = pred ? 16 : 0;
    asm volatile("cp.async.cg.shared.global [%0], [%1], 16, %2;\n"
        :: "r"(dst), "l"(src), "r"(sz));
}
__device__ __forceinline__ void cp_commit(){
    asm volatile("cp.async.commit_group;\n" ::: "memory");
}
template<int NW> __device__ __forceinline__ void cp_wait(){
    asm volatile("cp.async.wait_group %0;\n" :: "n"(NW) : "memory");
}

template<int BMT, int BNT>
__device__ __forceinline__ void fill_stage(uint32_t s0,
    const __nv_bfloat16* Ahi, const __nv_bfloat16* Alo,
    const __nv_bfloat16* Bhi, const __nv_bfloat16* Blo,
    int bm, int bn, int k0, int K, int N, int tid)
{
    constexpr int APLANE = BMT*80;
    constexpr int BPL = BNT*80;
    constexpr int ACH = 2*BMT*4;
    constexpr int TCH = ACH + 2*BNT*4;
    #pragma unroll
    for (int i = 0; i < TCH/256; i++){
        int idx = tid + i*256;
        if (idx < ACH){
            int plane = idx / (BMT*4);
            int r = (idx >> 2) % BMT;
            int ch = idx & 3;
            uint32_t dst = s0 + plane*APLANE + r*80 + ch*16;
            const __nv_bfloat16* base = plane ? Alo : Ahi;
            cp16(dst, base + (size_t)(bm + r)*K + k0 + ch*8, true);
        } else {
            int j = idx - ACH;
            int plane = j / (BNT*4);
            int r = (j >> 2) % BNT;
            int ch = j & 3;
            uint32_t dst = s0 + 2*APLANE + plane*BPL + r*80 + ch*16;
            const __nv_bfloat16* base = plane ? Blo : Bhi;
            int gn = bn + r;
            cp16(dst, base + (size_t)gn*K + k0 + ch*8, gn < N);
        }
    }
}

template<int BMT, int BNT>
__global__ void __launch_bounds__(256) gemm2(
    const __nv_bfloat16* __restrict__ Ahi, const __nv_bfloat16* __restrict__ Alo,
    const __nv_bfloat16* __restrict__ Bhi, const __nv_bfloat16* __restrict__ Blo,
    const float* __restrict__ bias, const float* __restrict__ res,
    float* __restrict__ Cf, __nv_bfloat16* __restrict__ Chi, __nv_bfloat16* __restrict__ Clo,
    int M, int N, int K, int doGelu)
{
    constexpr int APLANE = BMT*80;
    constexpr int BPL = BNT*80;
    constexpr int STAGE = 2*APLANE + 2*BPL;
    constexpr int MT = BMT/32;        // m16-tiles per warp
    constexpr int NT = BNT/32;        // n8-tiles per warp

    extern __shared__ char smem[];
    uint32_t sb = (uint32_t)__cvta_generic_to_shared(smem);
    int tid = threadIdx.x, lane = tid & 31, warp = tid >> 5;
    int bm = blockIdx.y * BMT, bn = blockIdx.x * BNT;
    int wm = (warp >> 2) * (BMT/2);   // warp grid 2(m) x 4(n)
    int wn = (warp & 3) * (BNT/4);

    float acc[MT][NT][4];
    #pragma unroll
    for (int i = 0; i < MT; i++)
        #pragma unroll
        for (int j = 0; j < NT; j++)
            #pragma unroll
            for (int f = 0; f < 4; f++) acc[i][j][f] = 0.0f;

    int niter = K / 32;
    fill_stage<BMT,BNT>(sb, Ahi, Alo, Bhi, Blo, bm, bn, 0, K, N, tid);
    cp_commit();

    for (int it = 0; it < niter; it++){
        // my own groups for stage it%2 have landed after this wait; the
        // barrier makes everyone's visible (and proves all warps finished
        // compute of it-1, so refilling buffer (it+1)&1 is safe).
        cp_wait<0>();
        __syncthreads();
        if (it + 1 < niter){
            fill_stage<BMT,BNT>(sb + ((it+1)&1)*STAGE, Ahi, Alo, Bhi, Blo,
                                bm, bn, (it+1)*32, K, N, tid);
            cp_commit();
        }

        const char* st = smem + (it & 1)*STAGE;
        const __nv_bfloat16* As_hi = (const __nv_bfloat16*)(st);
        const __nv_bfloat16* As_lo = (const __nv_bfloat16*)(st + APLANE);
        const __nv_bfloat16* Bs_hi = (const __nv_bfloat16*)(st + 2*APLANE);
        const __nv_bfloat16* Bs_lo = (const __nv_bfloat16*)(st + 2*APLANE + BPL);

        #pragma unroll
        for (int ks = 0; ks < 2; ks++){
            uint32_t ah[MT][4], al[MT][4], bh[NT][2], bl[NT][2];
            #pragma unroll
            for (int j = 0; j < BNT/64; j++){
                uint32_t r[4];
                int row = wn + j*16 + (lane & 15);
                int col = ks*16 + (lane >> 4)*8;
                ldsm4(r, Bs_hi + row*LDSH + col);
                bh[2*j][0]=r[0]; bh[2*j][1]=r[2]; bh[2*j+1][0]=r[1]; bh[2*j+1][1]=r[3];
                ldsm4(r, Bs_lo + row*LDSH + col);
                bl[2*j][0]=r[0]; bl[2*j][1]=r[2]; bl[2*j+1][0]=r[1]; bl[2*j+1][1]=r[3];
            }
            #pragma unroll
            for (int mt = 0; mt < MT; mt++){
                int row = wm + mt*16 + (lane & 15);
                int col = ks*16 + (lane >> 4)*8;
                ldsm4(ah[mt], As_hi + row*LDSH + col);
                ldsm4(al[mt], As_lo + row*LDSH + col);
            }
            #pragma unroll
            for (int mt = 0; mt < MT; mt++)
                #pragma unroll
                for (int nt = 0; nt < NT; nt++)
                    mma_bf16(acc[mt][nt], ah[mt], bh[nt]);
            #pragma unroll
            for (int mt = 0; mt < MT; mt++)
                #pragma unroll
                for (int nt = 0; nt < NT; nt++)
                    mma_bf16(acc[mt][nt], ah[mt], bl[nt]);
            #pragma unroll
            for (int mt = 0; mt < MT; mt++)
                #pragma unroll
                for (int nt = 0; nt < NT; nt++)
                    mma_bf16(acc[mt][nt], al[mt], bh[nt]);
        }
    }

    // ---- epilogue ----
    #pragma unroll
    for (int mt = 0; mt < MT; mt++){
        #pragma unroll
        for (int nt = 0; nt < NT; nt++){
            int row0 = bm + wm + mt*16 + (lane >> 2);
            int col0 = bn + wn + nt*8 + 2*(lane & 3);
            #pragma unroll
            for (int f = 0; f < 4; f++){
                int gm = row0 + ((f >= 2) ? 8 : 0);
                int gn = col0 + (f & 1);
                if (gn < N){
                    float v = acc[mt][nt][f];
                    if (bias) v += bias[gn];
                    if (res)  v += res[(size_t)gm*N + gn];
                    if (doGelu) v = 0.5f*v*(1.0f + erff(v*0.70710678118654752f));
                    size_t o = (size_t)gm*N + gn;
                    if (Cf) Cf[o] = v;
                    if (Chi){
                        __nv_bfloat16 h, l;
                        split_bf16(v, h, l);
                        Chi[o] = h; Clo[o] = l;
                    }
                }
            }
        }
    }
}

// =====================================================================
// Flash-tiled causal attention (R15 version — verified)
// =====================================================================
#define FA_SMEM ((2*64*68 + 64*65)*4)

__global__ void __launch_bounds__(128) fattn_kernel(const float* __restrict__ qkv,
                                                    __nv_bfloat16* __restrict__ aoh,
                                                    __nv_bfloat16* __restrict__ aol){
    extern __shared__ float fs[];
    float* Ks = fs;                 // [64][68]
    float* Vs = fs + 64*68;         // [64][68]
    float* Ps = fs + 2*64*68;       // [64][65]

    int qt = blockIdx.x, hh = blockIdx.y, b = blockIdx.z;
    int tid = threadIdx.x;
    int q = tid >> 1, hf = tid & 1;
    int qg = qt*64 + q;
    const float* base = qkv + (size_t)b*TSZ*3*CSZ;

    float qr[32];
    {
        const float* qp = base + (size_t)qg*3*CSZ + hh*192 + hf*32;
        #pragma unroll
        for (int i = 0; i < 8; i++){
            float4 v = *(const float4*)(qp + i*4);
            qr[i*4+0] = v.x*0.125f; qr[i*4+1] = v.y*0.125f;
            qr[i*4+2] = v.z*0.125f; qr[i*4+3] = v.w*0.125f;
        }
    }
    float o[32];
    #pragma unroll
    for (int i = 0; i < 32; i++) o[i] = 0.0f;
    float m = -1e30f, l = 0.0f;

    for (int st = 0; st <= qt; st++){
        int s0 = st*64;
        __syncthreads();
        #pragma unroll
        for (int i = 0; i < 8; i++){
            int idx = tid + i*128;
            int r = idx >> 4, ch = idx & 15;
            const float* kp = base + (size_t)(s0+r)*3*CSZ + hh*192 + 64 + ch*4;
            *(float4*)&Ks[r*68 + ch*4] = *(const float4*)kp;
            *(float4*)&Vs[r*68 + ch*4] = *(const float4*)(kp + 64);
        }
        __syncthreads();

        bool diag = (st == qt);
        float mt_ = -1e30f;
        #pragma unroll 4
        for (int s = 0; s < 64; s++){
            const float* kr = &Ks[s*68 + hf*32];
            float p = 0.0f;
            #pragma unroll
            for (int i = 0; i < 8; i++){
                float4 kv = *(const float4*)(kr + i*4);
                p = fmaf(qr[i*4+0], kv.x, p);
                p = fmaf(qr[i*4+1], kv.y, p);
                p = fmaf(qr[i*4+2], kv.z, p);
                p = fmaf(qr[i*4+3], kv.w, p);
            }
            p += __shfl_xor_sync(0xffffffffu, p, 1);
            if (diag && (s0 + s) > qg) p = -1e30f;
            if (hf == 0) Ps[q*65 + s] = p;
            mt_ = fmaxf(mt_, p);
        }
        float mn = fmaxf(m, mt_);
        float sc = __expf(m - mn);
        l *= sc;
        #pragma unroll
        for (int i = 0; i < 32; i++) o[i] *= sc;
        m = mn;
        __syncwarp();
        #pragma unroll 4
        for (int s = 0; s < 64; s++){
            float e = __expf(Ps[q*65 + s] - m);
            l += e;
            const float* vr = &Vs[s*68 + hf*32];
            #pragma unroll
            for (int i = 0; i < 8; i++){
                float4 vv = *(const float4*)(vr + i*4);
                o[i*4+0] = fmaf(e, vv.x, o[i*4+0]);
                o[i*4+1] = fmaf(e, vv.y, o[i*4+1]);
                o[i*4+2] = fmaf(e, vv.z, o[i*4+2]);
                o[i*4+3] = fmaf(e, vv.w, o[i*4+3]);
            }
        }
    }

    float inv = 1.0f / l;
    size_t ob = ((size_t)(b*TSZ + qg))*CSZ + hh*64 + hf*32;
    #pragma unroll
    for (int i = 0; i < 32; i++){
        float v = o[i]*inv;
        __nv_bfloat16 h, lo;
        split_bf16(v, h, lo);
        aoh[ob + i] = h;
        aol[ob + i] = lo;
    }
}

// ---------------- launch ----------------
extern "C" void kernel_launch(void* const* d_in, const int* in_sizes, int n_in,
                              void* d_out, int out_size)
{
    const int*   idx    = (const int*)  d_in[0];
    const float* wte    = (const float*)d_in[1];
    const float* wpe    = (const float*)d_in[2];
    const float* ln1_g  = (const float*)d_in[3];
    const float* ln1_b  = (const float*)d_in[4];
    const float* attn_w = (const float*)d_in[5];
    const float* attn_b = (const float*)d_in[6];
    const float* proj_w = (const float*)d_in[7];
    const float* proj_b = (const float*)d_in[8];
    const float* ln2_g  = (const float*)d_in[9];
    const float* ln2_b  = (const float*)d_in[10];
    const float* fc_w   = (const float*)d_in[11];
    const float* fc_b   = (const float*)d_in[12];
    const float* fp_w   = (const float*)d_in[13];
    const float* fp_b   = (const float*)d_in[14];
    const float* lnf_g  = (const float*)d_in[15];
    const float* lnf_b  = (const float*)d_in[16];
    float* out = (float*)d_out;

    float *x, *qkv;
    cudaGetSymbolAddress((void**)&x,   g_x);
    cudaGetSymbolAddress((void**)&qkv, g_qkv);
    __nv_bfloat16 *hH, *hL, *aoH, *aoL, *hidH, *hidL;
    cudaGetSymbolAddress((void**)&hH,   g_h_hi);
    cudaGetSymbolAddress((void**)&hL,   g_h_lo);
    cudaGetSymbolAddress((void**)&aoH,  g_ao_hi);
    cudaGetSymbolAddress((void**)&aoL,  g_ao_lo);
    cudaGetSymbolAddress((void**)&hidH, g_hid_hi);
    cudaGetSymbolAddress((void**)&hidL, g_hid_lo);
    __nv_bfloat16 *atH, *atL, *prH, *prL, *fcH, *fcL, *fpH, *fpL, *wtH, *wtL;
    cudaGetSymbolAddress((void**)&atH, g_attnT_hi);
    cudaGetSymbolAddress((void**)&atL, g_attnT_lo);
    cudaGetSymbolAddress((void**)&prH, g_projT_hi);
    cudaGetSymbolAddress((void**)&prL, g_projT_lo);
    cudaGetSymbolAddress((void**)&fcH, g_fcT_hi);
    cudaGetSymbolAddress((void**)&fcL, g_fcT_lo);
    cudaGetSymbolAddress((void**)&fpH, g_fpT_hi);
    cudaGetSymbolAddress((void**)&fpL, g_fpT_lo);
    cudaGetSymbolAddress((void**)&wtH, g_wte_hi);
    cudaGetSymbolAddress((void**)&wtL, g_wte_lo);

    const int GS_BIG   = 2*(2*128*80 + 2*128*80);   // 81920 (128x128 tile)
    const int GS_SMALL = 2*(2*128*80 + 2*64*80);    // 61440 (128x64 tile)
    cudaFuncSetAttribute((gemm2<128,128>), cudaFuncAttributeMaxDynamicSharedMemorySize, GS_BIG);
    cudaFuncSetAttribute((gemm2<128,64>),  cudaFuncAttributeMaxDynamicSharedMemorySize, GS_SMALL);
    cudaFuncSetAttribute(fattn_kernel, cudaFuncAttributeMaxDynamicSharedMemorySize, FA_SMEM);

    // 1: fused weight conversion (single launch)
    convw_kernel<<<NT_ALL, 256>>>(attn_w, proj_w, fc_w, fp_w, wte,
                                  atH, atL, prH, prL, fcH, fcL, fpH, fpL, wtH, wtL);
    // 2: embedding
    embed_kernel<<<(BT*CSZ + 255)/256, 256>>>(idx, wte, wpe, x);

    for (int l = 0; l < LSZ; l++){
        size_t oA = (size_t)l*3*CSZ*CSZ, oP = (size_t)l*CSZ*CSZ;
        size_t oF = (size_t)l*4*CSZ*CSZ;
        // attention
        ln_kernel<<<BT, 256>>>(x, ln1_g + (size_t)l*CSZ, ln1_b + (size_t)l*CSZ, hH, hL);
        gemm2<128,128><<<dim3(3*CSZ/128, BT/128), 256, GS_BIG>>>(
            hH, hL, atH + oA, atL + oA, attn_b + (size_t)l*3*CSZ,
            nullptr, qkv, nullptr, nullptr, BT, 3*CSZ, CSZ, 0);
        fattn_kernel<<<dim3(TSZ/64, HSZ, BSZ), 128, FA_SMEM>>>(qkv, aoH, aoL);
        gemm2<128,64><<<dim3(CSZ/64, BT/128), 256, GS_SMALL>>>(
            aoH, aoL, prH + oP, prL + oP, proj_b + (size_t)l*CSZ,
            x, x, nullptr, nullptr, BT, CSZ, CSZ, 0);
        // MLP
        ln_kernel<<<BT, 256>>>(x, ln2_g + (size_t)l*CSZ, ln2_b + (size_t)l*CSZ, hH, hL);
        gemm2<128,128><<<dim3(4*CSZ/128, BT/128), 256, GS_BIG>>>(
            hH, hL, fcH + oF, fcL + oF, fc_b + (size_t)l*4*CSZ,
            nullptr, nullptr, hidH, hidL, BT, 4*CSZ, CSZ, 1);
        gemm2<128,64><<<dim3(CSZ/64, BT/128), 256, GS_SMALL>>>(
            hidH, hidL, fpH + oF, fpL + oF, fp_b + (size_t)l*CSZ,
            x, x, nullptr, nullptr, BT, CSZ, 4*CSZ, 0);
    }

    // final LN + tied-embedding logits head
    ln_kernel<<<BT, 256>>>(x, lnf_g, lnf_b, hH, hL);
    gemm2<128,128><<<dim3((VSZ + 127)/128, BT/128), 256, GS_BIG>>>(
        hH, hL, wtH, wtL, nullptr, nullptr, out, nullptr, nullptr, BT, VSZ, CSZ, 0);
}